// round 1
// baseline (speedup 1.0000x reference)
#include <cuda_runtime.h>

#define HEADS 4
#define CHEAD 32
#define CIN   256
#define CHID  128
#define NTOK  4096
#define BATCH 4

typedef unsigned long long u64;

// Scratch (static device arrays: allocation-free per harness rules)
__device__ float g_q[BATCH * HEADS * NTOK * CHEAD];     // [bh][n][c], pre-scaled by 1/sqrt(32)
__device__ float g_k[BATCH * HEADS * NTOK * CHEAD];     // [bh][n][c]
__device__ float g_v[BATCH * HEADS * NTOK * CHEAD];     // [bh][n][c]
__device__ float g_attn[BATCH * CHID * NTOK];           // [b][h*32+c][n]

// ---- packed f32x2 helpers (Blackwell) ----
__device__ __forceinline__ u64 pk2(float lo, float hi) {
    u64 r; asm("mov.b64 %0,{%1,%2};" : "=l"(r) : "f"(lo), "f"(hi)); return r;
}
__device__ __forceinline__ void upk2(u64 a, float& lo, float& hi) {
    asm("mov.b64 {%0,%1},%2;" : "=f"(lo), "=f"(hi) : "l"(a));
}
__device__ __forceinline__ u64 ffma2(u64 a, u64 b, u64 c) {
    u64 d; asm("fma.rn.f32x2 %0,%1,%2,%3;" : "=l"(d) : "l"(a), "l"(b), "l"(c)); return d;
}
__device__ __forceinline__ u64 fmul2(u64 a, u64 b) {
    u64 d; asm("mul.rn.f32x2 %0,%1,%2;" : "=l"(d) : "l"(a), "l"(b)); return d;
}

// ============================================================================
// Kernel 1: QKV projection.  qkv[o,n] = sum_c w[o,c] * x[c,n]  per batch.
// Writes q/k/v in [bh][n][32] layout; q pre-scaled by 32^-0.5.
// grid (N/64, 384/64, B), block (16,16), per-thread 4x4 tile.
// ============================================================================
__global__ __launch_bounds__(256) void qkv_kernel(const float* __restrict__ x,
                                                  const float* __restrict__ w)
{
    __shared__ float Asm[64][17];   // [o][k]
    __shared__ float Bsm[16][68];   // [k][n]
    int tx = threadIdx.x, ty = threadIdx.y;
    int t  = ty * 16 + tx;
    int n0 = blockIdx.x * 64;
    int o0 = blockIdx.y * 64;
    int b  = blockIdx.z;
    const float* xb = x + (size_t)b * CIN * NTOK;

    float acc[4][4];
    #pragma unroll
    for (int i = 0; i < 4; i++)
        #pragma unroll
        for (int j = 0; j < 4; j++) acc[i][j] = 0.f;

    int ra = t >> 2, ga = t & 3;    // A-tile loader: row (o), 4-col group (k)
    int rb = t >> 4, cb = t & 15;   // B-tile loader: row (k), 4-col group (n)

    for (int kt = 0; kt < CIN / 16; kt++) {
        float4 wv = *(const float4*)(w + (size_t)(o0 + ra) * CIN + kt * 16 + ga * 4);
        Asm[ra][ga * 4 + 0] = wv.x; Asm[ra][ga * 4 + 1] = wv.y;
        Asm[ra][ga * 4 + 2] = wv.z; Asm[ra][ga * 4 + 3] = wv.w;
        float4 xv = *(const float4*)(xb + (size_t)(kt * 16 + rb) * NTOK + n0 + cb * 4);
        *(float4*)&Bsm[rb][cb * 4] = xv;
        __syncthreads();
        #pragma unroll
        for (int k = 0; k < 16; k++) {
            float a0 = Asm[ty * 4 + 0][k], a1 = Asm[ty * 4 + 1][k];
            float a2 = Asm[ty * 4 + 2][k], a3 = Asm[ty * 4 + 3][k];
            float4 bv = *(const float4*)&Bsm[k][tx * 4];
            acc[0][0] += a0 * bv.x; acc[0][1] += a0 * bv.y; acc[0][2] += a0 * bv.z; acc[0][3] += a0 * bv.w;
            acc[1][0] += a1 * bv.x; acc[1][1] += a1 * bv.y; acc[1][2] += a1 * bv.z; acc[1][3] += a1 * bv.w;
            acc[2][0] += a2 * bv.x; acc[2][1] += a2 * bv.y; acc[2][2] += a2 * bv.z; acc[2][3] += a2 * bv.w;
            acc[3][0] += a3 * bv.x; acc[3][1] += a3 * bv.y; acc[3][2] += a3 * bv.z; acc[3][3] += a3 * bv.w;
        }
        __syncthreads();
    }

    // Epilogue: map o -> (kind, head, c); write float4 of 4 consecutive c.
    int obase = o0 + ty * 4;
    int kind  = obase >> 7;
    int rr    = obase & 127;
    int h     = rr >> 5, c = rr & 31;
    float* dst = (kind == 0) ? g_q : ((kind == 1) ? g_k : g_v);
    float sc   = (kind == 0) ? 0.17677669529663687f : 1.f;  // 32^-0.5 on q
    size_t hb  = ((size_t)(b * HEADS + h) * NTOK) * CHEAD + c;
    #pragma unroll
    for (int j = 0; j < 4; j++) {
        int n = n0 + tx * 4 + j;
        float4 v;
        v.x = acc[0][j] * sc; v.y = acc[1][j] * sc;
        v.z = acc[2][j] * sc; v.w = acc[3][j] * sc;
        *(float4*)&dst[hb + (size_t)n * CHEAD] = v;
    }
}

// ============================================================================
// Kernel 2: flash attention. 1 thread = 1 query. K/V tiles 64x32 in smem,
// processed in 4 sub-tiles of 16 keys so s[] stays in registers.
// grid (N/128, B*HEADS), block 128.
// ============================================================================
__global__ __launch_bounds__(128) void attn_kernel()
{
    __shared__ float Ksm[64 * 32];
    __shared__ float Vsm[64 * 32];
    int tid = threadIdx.x;
    int bh  = blockIdx.y;
    int n   = blockIdx.x * 128 + tid;

    const float* qp = g_q + ((size_t)bh * NTOK + n) * CHEAD;
    u64 q2[16], o2[16];
    #pragma unroll
    for (int w = 0; w < 8; w++) {
        float4 qv = ((const float4*)qp)[w];
        q2[2 * w]     = pk2(qv.x, qv.y);
        q2[2 * w + 1] = pk2(qv.z, qv.w);
    }
    u64 z = pk2(0.f, 0.f);
    #pragma unroll
    for (int w = 0; w < 16; w++) o2[w] = z;
    float m = -1e30f, l = 0.f;

    const float4* kg = (const float4*)(g_k + (size_t)bh * NTOK * CHEAD);
    const float4* vg = (const float4*)(g_v + (size_t)bh * NTOK * CHEAD);
    float4* Ks4 = (float4*)Ksm;
    float4* Vs4 = (float4*)Vsm;

    for (int kt = 0; kt < NTOK / 64; kt++) {
        int base = kt * 512;            // 64*32/4 float4 per tile
        #pragma unroll
        for (int u = 0; u < 4; u++) {
            Ks4[tid + u * 128] = kg[base + tid + u * 128];
            Vs4[tid + u * 128] = vg[base + tid + u * 128];
        }
        __syncthreads();

        for (int sub = 0; sub < 4; sub++) {     // not unrolled: keep I$ small
            float s[16];
            float tmax = -1e30f;
            #pragma unroll
            for (int jj = 0; jj < 16; jj++) {
                const float4* kr = (const float4*)(Ksm + (sub * 16 + jj) * 32);
                u64 acc = z;
                #pragma unroll
                for (int w2 = 0; w2 < 8; w2++) {
                    float4 kv = kr[w2];
                    acc = ffma2(q2[2 * w2],     pk2(kv.x, kv.y), acc);
                    acc = ffma2(q2[2 * w2 + 1], pk2(kv.z, kv.w), acc);
                }
                float lo, hi; upk2(acc, lo, hi);
                s[jj] = lo + hi;
                tmax  = fmaxf(tmax, s[jj]);
            }
            // online softmax update
            float mnew = fmaxf(m, tmax);
            float corr = __expf(m - mnew);
            m = mnew;
            l *= corr;
            u64 c2 = pk2(corr, corr);
            #pragma unroll
            for (int w2 = 0; w2 < 16; w2++) o2[w2] = fmul2(o2[w2], c2);
            #pragma unroll
            for (int jj = 0; jj < 16; jj++) {
                float p = __expf(s[jj] - m);
                l += p;
                u64 p2 = pk2(p, p);
                const float4* vr = (const float4*)(Vsm + (sub * 16 + jj) * 32);
                #pragma unroll
                for (int w2 = 0; w2 < 8; w2++) {
                    float4 vv = vr[w2];
                    o2[2 * w2]     = ffma2(p2, pk2(vv.x, vv.y), o2[2 * w2]);
                    o2[2 * w2 + 1] = ffma2(p2, pk2(vv.z, vv.w), o2[2 * w2 + 1]);
                }
            }
        }
        __syncthreads();
    }

    float inv = 1.f / l;
    // write channel-major [b][h*32+c][n]: lanes are consecutive n -> coalesced
    float* op = g_attn + (size_t)bh * 32 * NTOK + n;
    #pragma unroll
    for (int w = 0; w < 16; w++) {
        float lo, hi; upk2(o2[w], lo, hi);
        op[(size_t)(2 * w) * NTOK]     = lo * inv;
        op[(size_t)(2 * w + 1) * NTOK] = hi * inv;
    }
}

// ============================================================================
// Kernel 3: output projection.  out[o,n] = sum_c w_out[o,c]*attn[c,n] + b[o]
// grid (N/64, 256/64, B), block (16,16).
// ============================================================================
__global__ __launch_bounds__(256) void out_kernel(const float* __restrict__ w,
                                                  const float* __restrict__ bias,
                                                  float* __restrict__ out)
{
    __shared__ float Asm[64][17];
    __shared__ float Bsm[16][68];
    int tx = threadIdx.x, ty = threadIdx.y;
    int t  = ty * 16 + tx;
    int n0 = blockIdx.x * 64;
    int o0 = blockIdx.y * 64;
    int b  = blockIdx.z;
    const float* ab = g_attn + (size_t)b * CHID * NTOK;

    float acc[4][4];
    #pragma unroll
    for (int i = 0; i < 4; i++)
        #pragma unroll
        for (int j = 0; j < 4; j++) acc[i][j] = 0.f;

    int ra = t >> 2, ga = t & 3;
    int rb = t >> 4, cb = t & 15;

    for (int kt = 0; kt < CHID / 16; kt++) {
        float4 wv = *(const float4*)(w + (size_t)(o0 + ra) * CHID + kt * 16 + ga * 4);
        Asm[ra][ga * 4 + 0] = wv.x; Asm[ra][ga * 4 + 1] = wv.y;
        Asm[ra][ga * 4 + 2] = wv.z; Asm[ra][ga * 4 + 3] = wv.w;
        float4 xv = *(const float4*)(ab + (size_t)(kt * 16 + rb) * NTOK + n0 + cb * 4);
        *(float4*)&Bsm[rb][cb * 4] = xv;
        __syncthreads();
        #pragma unroll
        for (int k = 0; k < 16; k++) {
            float a0 = Asm[ty * 4 + 0][k], a1 = Asm[ty * 4 + 1][k];
            float a2 = Asm[ty * 4 + 2][k], a3 = Asm[ty * 4 + 3][k];
            float4 bv = *(const float4*)&Bsm[k][tx * 4];
            acc[0][0] += a0 * bv.x; acc[0][1] += a0 * bv.y; acc[0][2] += a0 * bv.z; acc[0][3] += a0 * bv.w;
            acc[1][0] += a1 * bv.x; acc[1][1] += a1 * bv.y; acc[1][2] += a1 * bv.z; acc[1][3] += a1 * bv.w;
            acc[2][0] += a2 * bv.x; acc[2][1] += a2 * bv.y; acc[2][2] += a2 * bv.z; acc[2][3] += a2 * bv.w;
            acc[3][0] += a3 * bv.x; acc[3][1] += a3 * bv.y; acc[3][2] += a3 * bv.z; acc[3][3] += a3 * bv.w;
        }
        __syncthreads();
    }

    #pragma unroll
    for (int i = 0; i < 4; i++) {
        int o = o0 + ty * 4 + i;
        float bb = bias[o];
        float4 v;
        v.x = acc[i][0] + bb; v.y = acc[i][1] + bb;
        v.z = acc[i][2] + bb; v.w = acc[i][3] + bb;
        *(float4*)&out[(size_t)(b * CIN + o) * NTOK + n0 + tx * 4] = v;
    }
}

// ============================================================================
extern "C" void kernel_launch(void* const* d_in, const int* in_sizes, int n_in,
                              void* d_out, int out_size)
{
    (void)in_sizes; (void)n_in; (void)out_size;
    const float* x     = (const float*)d_in[0];
    const float* w_qkv = (const float*)d_in[1];
    const float* w_out = (const float*)d_in[2];
    const float* b_out = (const float*)d_in[3];
    float* out = (float*)d_out;

    qkv_kernel<<<dim3(NTOK / 64, 384 / 64, BATCH), dim3(16, 16)>>>(x, w_qkv);
    attn_kernel<<<dim3(NTOK / 128, BATCH * HEADS), 128>>>();
    out_kernel<<<dim3(NTOK / 64, CIN / 64, BATCH), dim3(16, 16)>>>(w_out, b_out, out);
}

// round 3
// speedup vs baseline: 2.8124x; 2.8124x over previous
#include <cuda_runtime.h>
#include <cuda_bf16.h>

#define HEADS 4
#define CHEAD 32
#define CIN   256
#define CHID  128
#define NTOK  4096
#define BATCH 4
#define BH    (BATCH * HEADS)

// q scale folded with log2(e) so softmax uses ex2 directly
#define QSCALE ((float)(0.17677669529663687 * 1.4426950408889634))

// ---------------- device scratch (allocation-free) ----------------
// q/k/v: [bh][n][32] as bf16 pairs -> 16 uint = 4 uint4 per row
__device__ uint4 g_qhi[BH * NTOK * 4];
__device__ uint4 g_qlo[BH * NTOK * 4];
__device__ uint4 g_khi[BH * NTOK * 4];
__device__ uint4 g_klo[BH * NTOK * 4];
__device__ uint4 g_vhi[BH * NTOK * 4];
__device__ uint4 g_vlo[BH * NTOK * 4];
// attention output fp32 [b][h*32+c][n]
__device__ float g_attn[BATCH * CHID * NTOK];

// ---------------- helpers ----------------
__device__ __forceinline__ unsigned s2u(const void* p) {
    unsigned r;
    asm("{.reg .u64 t; cvta.to.shared.u64 t,%1; cvt.u32.u64 %0,t;}" : "=r"(r) : "l"(p));
    return r;
}
__device__ __forceinline__ float ex2f(float x) {
    float y; asm("ex2.approx.f32 %0,%1;" : "=f"(y) : "f"(x)); return y;
}
// split (a,b) fp32 -> bf16x2 hi (lo-half=a) + bf16x2 residual
__device__ __forceinline__ void split2(float a, float b, unsigned& h, unsigned& l) {
    unsigned hh; asm("cvt.rn.bf16x2.f32 %0,%1,%2;" : "=r"(hh) : "f"(b), "f"(a));
    float ha = __uint_as_float(hh << 16);
    float hb = __uint_as_float(hh & 0xffff0000u);
    float ra = a - ha, rb = b - hb;
    unsigned ll; asm("cvt.rn.bf16x2.f32 %0,%1,%2;" : "=r"(ll) : "f"(rb), "f"(ra));
    h = hh; l = ll;
}

#define MMA_BF16(d, a0, a1, a2, a3, b0, b1) \
    asm volatile("mma.sync.aligned.m16n8k16.row.col.f32.bf16.bf16.f32 " \
        "{%0,%1,%2,%3},{%4,%5,%6,%7},{%8,%9},{%0,%1,%2,%3};" \
        : "+f"((d)[0]), "+f"((d)[1]), "+f"((d)[2]), "+f"((d)[3]) \
        : "r"(a0), "r"(a1), "r"(a2), "r"(a3), "r"(b0), "r"(b1))

#define LDSM_X4(r0, r1, r2, r3, a) \
    asm volatile("ldmatrix.sync.aligned.m8n8.x4.shared.b16 {%0,%1,%2,%3},[%4];" \
        : "=r"(r0), "=r"(r1), "=r"(r2), "=r"(r3) : "r"(a))
#define LDSM_X4_T(r0, r1, r2, r3, a) \
    asm volatile("ldmatrix.sync.aligned.m8n8.x4.trans.shared.b16 {%0,%1,%2,%3},[%4];" \
        : "=r"(r0), "=r"(r1), "=r"(r2), "=r"(r3) : "r"(a))

#define CP_ASYNC(dst, src) \
    asm volatile("cp.async.cg.shared.global [%0],[%1],16;" :: "r"(dst), "l"(src))
#define CP_COMMIT() asm volatile("cp.async.commit_group;")
#define CP_WAIT(n)  asm volatile("cp.async.wait_group %0;" :: "n"(n) : "memory")

// ============================================================================
// Kernel 1: QKV projection -> bf16 hi/lo split, all in [bh][n][32] layout
// ============================================================================
__global__ __launch_bounds__(256) void qkv_kernel(const float* __restrict__ x,
                                                  const float* __restrict__ w)
{
    __shared__ float Asm[64][17];
    __shared__ float Bsm[16][68];
    int tx = threadIdx.x, ty = threadIdx.y;
    int t  = ty * 16 + tx;
    int n0 = blockIdx.x * 64;
    int o0 = blockIdx.y * 64;
    int b  = blockIdx.z;
    const float* xb = x + (size_t)b * CIN * NTOK;

    float acc[4][4];
    #pragma unroll
    for (int i = 0; i < 4; i++)
        #pragma unroll
        for (int j = 0; j < 4; j++) acc[i][j] = 0.f;

    int ra = t >> 2, ga = t & 3;
    int rb = t >> 4, cb = t & 15;

    for (int kt = 0; kt < CIN / 16; kt++) {
        float4 wv = *(const float4*)(w + (size_t)(o0 + ra) * CIN + kt * 16 + ga * 4);
        Asm[ra][ga * 4 + 0] = wv.x; Asm[ra][ga * 4 + 1] = wv.y;
        Asm[ra][ga * 4 + 2] = wv.z; Asm[ra][ga * 4 + 3] = wv.w;
        float4 xv = *(const float4*)(xb + (size_t)(kt * 16 + rb) * NTOK + n0 + cb * 4);
        *(float4*)&Bsm[rb][cb * 4] = xv;
        __syncthreads();
        #pragma unroll
        for (int k = 0; k < 16; k++) {
            float a0 = Asm[ty * 4 + 0][k], a1 = Asm[ty * 4 + 1][k];
            float a2 = Asm[ty * 4 + 2][k], a3 = Asm[ty * 4 + 3][k];
            float4 bv = *(const float4*)&Bsm[k][tx * 4];
            acc[0][0] += a0 * bv.x; acc[0][1] += a0 * bv.y; acc[0][2] += a0 * bv.z; acc[0][3] += a0 * bv.w;
            acc[1][0] += a1 * bv.x; acc[1][1] += a1 * bv.y; acc[1][2] += a1 * bv.z; acc[1][3] += a1 * bv.w;
            acc[2][0] += a2 * bv.x; acc[2][1] += a2 * bv.y; acc[2][2] += a2 * bv.z; acc[2][3] += a2 * bv.w;
            acc[3][0] += a3 * bv.x; acc[3][1] += a3 * bv.y; acc[3][2] += a3 * bv.z; acc[3][3] += a3 * bv.w;
        }
        __syncthreads();
    }

    int obase = o0 + ty * 4;
    int kind  = obase >> 7;      // 0=q, 1=k, 2=v
    int rr    = obase & 127;
    int h     = rr >> 5, c = rr & 31;
    int bhI   = b * HEADS + h;

    float sc = (kind == 0) ? QSCALE : 1.f;
    uint2* dhi = (uint2*)((kind == 0) ? g_qhi : (kind == 1) ? g_khi : g_vhi);
    uint2* dlo = (uint2*)((kind == 0) ? g_qlo : (kind == 1) ? g_klo : g_vlo);
    #pragma unroll
    for (int j = 0; j < 4; j++) {
        int n = n0 + tx * 4 + j;
        unsigned h0, l0, h1, l1;
        split2(acc[0][j] * sc, acc[1][j] * sc, h0, l0);
        split2(acc[2][j] * sc, acc[3][j] * sc, h1, l1);
        size_t idx = ((size_t)bhI * NTOK + n) * 8 + (c >> 2);
        dhi[idx] = make_uint2(h0, h1);
        dlo[idx] = make_uint2(l0, l1);
    }
}

// ============================================================================
// Kernel 2: FlashAttention-2 with mma.sync bf16x3.
// CTA: 4 warps, 64 queries (16/warp); key tiles of 64, double-buffered cp.async.
// smem row stride 80B -> ldmatrix conflict-free.
// ============================================================================
#define ROWB 80
#define ARRB (64 * ROWB)        // 5120 per array
#define BUFB (4 * ARRB)         // 20480 per buffer (Khi,Klo,Vhi,Vlo)

struct __align__(16) FSmem { unsigned char kv[2][4][ARRB]; };

__global__ __launch_bounds__(128) void fattn_kernel()
{
    __shared__ FSmem fs;
    unsigned sb = s2u(&fs);
    int tid = threadIdx.x;
    int lane = tid & 31, wid = tid >> 5;
    int qt = blockIdx.x, bh = blockIdx.y;
    int g = lane >> 2, tq = lane & 3;          // quad row / thread-in-quad
    int lrow = lane & 7, lmi = lane >> 3;      // ldmatrix addressing

    const uint4* srcs[4] = {
        g_khi + (size_t)bh * NTOK * 4, g_klo + (size_t)bh * NTOK * 4,
        g_vhi + (size_t)bh * NTOK * 4, g_vlo + (size_t)bh * NTOK * 4 };

    // prefetch tile 0
    {
        int c16 = tid & 3, r0 = tid >> 2;
        #pragma unroll
        for (int i = 0; i < 8; i++) {
            int arr = i >> 1, row = (r0 + i * 32) & 63;
            unsigned dst = sb + arr * ARRB + row * ROWB + c16 * 16;
            CP_ASYNC(dst, srcs[arr] + (size_t)row * 4 + c16);
        }
        CP_COMMIT();
    }

    // ---- load Q fragments (hi/lo), 2 k-blocks ----
    unsigned qh[2][4], ql[2][4];
    {
        int qa = qt * 64 + wid * 16 + g;
        const unsigned* ph = (const unsigned*)(g_qhi + ((size_t)bh * NTOK + qa) * 4);
        const unsigned* pl = (const unsigned*)(g_qlo + ((size_t)bh * NTOK + qa) * 4);
        #pragma unroll
        for (int kb = 0; kb < 2; kb++) {
            qh[kb][0] = ph[8 * kb + tq];       qh[kb][2] = ph[8 * kb + 4 + tq];
            qh[kb][1] = ph[128 + 8 * kb + tq]; qh[kb][3] = ph[128 + 8 * kb + 4 + tq];
            ql[kb][0] = pl[8 * kb + tq];       ql[kb][2] = pl[8 * kb + 4 + tq];
            ql[kb][1] = pl[128 + 8 * kb + tq]; ql[kb][3] = pl[128 + 8 * kb + 4 + tq];
        }
    }

    float o[4][4];
    #pragma unroll
    for (int i = 0; i < 4; i++)
        #pragma unroll
        for (int j = 0; j < 4; j++) o[i][j] = 0.f;
    float m_a = -1e30f, m_b = -1e30f, l_a = 0.f, l_b = 0.f;

    int buf = 0;
    for (int kt = 0; kt < NTOK / 64; kt++) {
        if (kt < NTOK / 64 - 1) {       // prefetch next tile into other buffer
            int c16 = tid & 3, r0 = tid >> 2;
            unsigned bb = sb + (buf ^ 1) * BUFB;
            size_t goff = (size_t)(kt + 1) * 64 * 4;
            #pragma unroll
            for (int i = 0; i < 8; i++) {
                int arr = i >> 1, row = (r0 + i * 32) & 63;
                CP_ASYNC(bb + arr * ARRB + row * ROWB + c16 * 16,
                         srcs[arr] + goff + (size_t)row * 4 + c16);
            }
            CP_COMMIT();
            CP_WAIT(1);
        } else {
            CP_WAIT(0);
        }
        __syncthreads();

        unsigned kb_base = sb + buf * BUFB;

        // ---- S = Qhi*Khi + Qlo*Khi + Qhi*Klo ----
        float s[8][4];
        #pragma unroll
        for (int nb = 0; nb < 8; nb++)
            #pragma unroll
            for (int i = 0; i < 4; i++) s[nb][i] = 0.f;

        #pragma unroll
        for (int nb = 0; nb < 8; nb++) {
            unsigned kh0, kh1, kh2, kh3, kl0, kl1, kl2, kl3;
            unsigned ka = kb_base + (8 * nb + lrow) * ROWB + lmi * 16;
            LDSM_X4(kh0, kh1, kh2, kh3, ka);
            LDSM_X4(kl0, kl1, kl2, kl3, ka + ARRB);
            MMA_BF16(s[nb], qh[0][0], qh[0][1], qh[0][2], qh[0][3], kh0, kh1);
            MMA_BF16(s[nb], qh[1][0], qh[1][1], qh[1][2], qh[1][3], kh2, kh3);
            MMA_BF16(s[nb], ql[0][0], ql[0][1], ql[0][2], ql[0][3], kh0, kh1);
            MMA_BF16(s[nb], ql[1][0], ql[1][1], ql[1][2], ql[1][3], kh2, kh3);
            MMA_BF16(s[nb], qh[0][0], qh[0][1], qh[0][2], qh[0][3], kl0, kl1);
            MMA_BF16(s[nb], qh[1][0], qh[1][1], qh[1][2], qh[1][3], kl2, kl3);
        }

        // ---- online softmax ----
        float mx_a = -1e30f, mx_b = -1e30f;
        #pragma unroll
        for (int nb = 0; nb < 8; nb++) {
            mx_a = fmaxf(mx_a, fmaxf(s[nb][0], s[nb][1]));
            mx_b = fmaxf(mx_b, fmaxf(s[nb][2], s[nb][3]));
        }
        mx_a = fmaxf(mx_a, __shfl_xor_sync(0xffffffffu, mx_a, 1));
        mx_a = fmaxf(mx_a, __shfl_xor_sync(0xffffffffu, mx_a, 2));
        mx_b = fmaxf(mx_b, __shfl_xor_sync(0xffffffffu, mx_b, 1));
        mx_b = fmaxf(mx_b, __shfl_xor_sync(0xffffffffu, mx_b, 2));

        float mna = fmaxf(m_a, mx_a), mnb = fmaxf(m_b, mx_b);
        float ca = ex2f(m_a - mna), cb = ex2f(m_b - mnb);
        m_a = mna; m_b = mnb;
        #pragma unroll
        for (int nb = 0; nb < 4; nb++) {
            o[nb][0] *= ca; o[nb][1] *= ca;
            o[nb][2] *= cb; o[nb][3] *= cb;
        }

        float sa = 0.f, sbm = 0.f;
        #pragma unroll
        for (int nb = 0; nb < 8; nb++) {
            s[nb][0] = ex2f(s[nb][0] - m_a);
            s[nb][1] = ex2f(s[nb][1] - m_a);
            s[nb][2] = ex2f(s[nb][2] - m_b);
            s[nb][3] = ex2f(s[nb][3] - m_b);
            sa += s[nb][0] + s[nb][1];
            sbm += s[nb][2] + s[nb][3];
        }
        sa += __shfl_xor_sync(0xffffffffu, sa, 1);
        sa += __shfl_xor_sync(0xffffffffu, sa, 2);
        sbm += __shfl_xor_sync(0xffffffffu, sbm, 1);
        sbm += __shfl_xor_sync(0xffffffffu, sbm, 2);
        l_a = l_a * ca + sa;
        l_b = l_b * cb + sbm;

        // ---- O += Phi*Vhi + Plo*Vhi + Phi*Vlo ----
        unsigned vbase = kb_base + 2 * ARRB;
        #pragma unroll
        for (int kb = 0; kb < 4; kb++) {
            unsigned ph[4], pl[4];
            split2(s[2 * kb][0],     s[2 * kb][1],     ph[0], pl[0]);
            split2(s[2 * kb][2],     s[2 * kb][3],     ph[1], pl[1]);
            split2(s[2 * kb + 1][0], s[2 * kb + 1][1], ph[2], pl[2]);
            split2(s[2 * kb + 1][2], s[2 * kb + 1][3], ph[3], pl[3]);
            #pragma unroll
            for (int cp = 0; cp < 2; cp++) {
                // matrices: (oct = 2kb + (mi&1), chunk = 2cp + (mi>>1))
                int oct = 2 * kb + (lmi & 1), chunk = 2 * cp + (lmi >> 1);
                unsigned va = vbase + (oct * 8 + lrow) * ROWB + chunk * 16;
                unsigned vh0, vh1, vh2, vh3, vl0, vl1, vl2, vl3;
                LDSM_X4_T(vh0, vh1, vh2, vh3, va);
                LDSM_X4_T(vl0, vl1, vl2, vl3, va + ARRB);
                MMA_BF16(o[2 * cp],     ph[0], ph[1], ph[2], ph[3], vh0, vh1);
                MMA_BF16(o[2 * cp + 1], ph[0], ph[1], ph[2], ph[3], vh2, vh3);
                MMA_BF16(o[2 * cp],     pl[0], pl[1], pl[2], pl[3], vh0, vh1);
                MMA_BF16(o[2 * cp + 1], pl[0], pl[1], pl[2], pl[3], vh2, vh3);
                MMA_BF16(o[2 * cp],     ph[0], ph[1], ph[2], ph[3], vl0, vl1);
                MMA_BF16(o[2 * cp + 1], ph[0], ph[1], ph[2], ph[3], vl2, vl3);
            }
        }

        __syncthreads();     // done reading buf before it is overwritten
        buf ^= 1;
    }

    // ---- epilogue: normalize, transpose via smem, coalesced store ----
    float inv_a = 1.f / l_a, inv_b = 1.f / l_b;
    float* Osm = (float*)&fs;          // 64 rows x 34 floats
    int qa = wid * 16 + g;
    #pragma unroll
    for (int nb = 0; nb < 4; nb++) {
        *(float2*)&Osm[qa * 34 + 8 * nb + 2 * tq] =
            make_float2(o[nb][0] * inv_a, o[nb][1] * inv_a);
        *(float2*)&Osm[(qa + 8) * 34 + 8 * nb + 2 * tq] =
            make_float2(o[nb][2] * inv_b, o[nb][3] * inv_b);
    }
    __syncthreads();

    int n0 = qt * 64;
    int qq = tid & 63;
    #pragma unroll
    for (int it = 0; it < 16; it++) {
        int c = it * 2 + (tid >> 6);
        g_attn[((size_t)bh * CHEAD + c) * NTOK + n0 + qq] = Osm[qq * 34 + c];
    }
}

// ============================================================================
// Kernel 3: output projection
// ============================================================================
__global__ __launch_bounds__(256) void out_kernel(const float* __restrict__ w,
                                                  const float* __restrict__ bias,
                                                  float* __restrict__ out)
{
    __shared__ float Asm[64][17];
    __shared__ float Bsm[16][68];
    int tx = threadIdx.x, ty = threadIdx.y;
    int t  = ty * 16 + tx;
    int n0 = blockIdx.x * 64;
    int o0 = blockIdx.y * 64;
    int b  = blockIdx.z;
    const float* ab = g_attn + (size_t)b * CHID * NTOK;

    float acc[4][4];
    #pragma unroll
    for (int i = 0; i < 4; i++)
        #pragma unroll
        for (int j = 0; j < 4; j++) acc[i][j] = 0.f;

    int ra = t >> 2, ga = t & 3;
    int rb = t >> 4, cb = t & 15;

    for (int kt = 0; kt < CHID / 16; kt++) {
        float4 wv = *(const float4*)(w + (size_t)(o0 + ra) * CHID + kt * 16 + ga * 4);
        Asm[ra][ga * 4 + 0] = wv.x; Asm[ra][ga * 4 + 1] = wv.y;
        Asm[ra][ga * 4 + 2] = wv.z; Asm[ra][ga * 4 + 3] = wv.w;
        float4 xv = *(const float4*)(ab + (size_t)(kt * 16 + rb) * NTOK + n0 + cb * 4);
        *(float4*)&Bsm[rb][cb * 4] = xv;
        __syncthreads();
        #pragma unroll
        for (int k = 0; k < 16; k++) {
            float a0 = Asm[ty * 4 + 0][k], a1 = Asm[ty * 4 + 1][k];
            float a2 = Asm[ty * 4 + 2][k], a3 = Asm[ty * 4 + 3][k];
            float4 bv = *(const float4*)&Bsm[k][tx * 4];
            acc[0][0] += a0 * bv.x; acc[0][1] += a0 * bv.y; acc[0][2] += a0 * bv.z; acc[0][3] += a0 * bv.w;
            acc[1][0] += a1 * bv.x; acc[1][1] += a1 * bv.y; acc[1][2] += a1 * bv.z; acc[1][3] += a1 * bv.w;
            acc[2][0] += a2 * bv.x; acc[2][1] += a2 * bv.y; acc[2][2] += a2 * bv.z; acc[2][3] += a2 * bv.w;
            acc[3][0] += a3 * bv.x; acc[3][1] += a3 * bv.y; acc[3][2] += a3 * bv.z; acc[3][3] += a3 * bv.w;
        }
        __syncthreads();
    }

    #pragma unroll
    for (int i = 0; i < 4; i++) {
        int oo = o0 + ty * 4 + i;
        float bb = bias[oo];
        float4 v;
        v.x = acc[i][0] + bb; v.y = acc[i][1] + bb;
        v.z = acc[i][2] + bb; v.w = acc[i][3] + bb;
        *(float4*)&out[(size_t)(b * CIN + oo) * NTOK + n0 + tx * 4] = v;
    }
}

// ============================================================================
extern "C" void kernel_launch(void* const* d_in, const int* in_sizes, int n_in,
                              void* d_out, int out_size)
{
    (void)in_sizes; (void)n_in; (void)out_size;
    const float* x     = (const float*)d_in[0];
    const float* w_qkv = (const float*)d_in[1];
    const float* w_out = (const float*)d_in[2];
    const float* b_out = (const float*)d_in[3];
    float* out = (float*)d_out;

    qkv_kernel<<<dim3(NTOK / 64, 384 / 64, BATCH), dim3(16, 16)>>>(x, w_qkv);
    fattn_kernel<<<dim3(NTOK / 64, BH), 128>>>();
    out_kernel<<<dim3(NTOK / 64, CIN / 64, BATCH), dim3(16, 16)>>>(w_out, b_out, out);
}

// round 4
// speedup vs baseline: 3.3643x; 1.1963x over previous
#include <cuda_runtime.h>
#include <cuda_bf16.h>

#define HEADS 4
#define CHEAD 32
#define CIN   256
#define CHID  128
#define NTOK  4096
#define BATCH 4
#define BH    (BATCH * HEADS)

#define QSCALE ((float)(0.17677669529663687 * 1.4426950408889634))

// ---------------- device scratch ----------------
__device__ unsigned g_xhi[BATCH * CIN * NTOK / 2];
__device__ unsigned g_xlo[BATCH * CIN * NTOK / 2];
__device__ unsigned g_wqhi[384 * 256 / 2];
__device__ unsigned g_wqlo[384 * 256 / 2];
__device__ unsigned g_wohi[256 * 128 / 2];
__device__ unsigned g_wolo[256 * 128 / 2];
// q/k/v: [bh][n][32] bf16 pairs (16 uint per row)
__device__ uint4 g_qhi[BH * NTOK * 4];
__device__ uint4 g_qlo[BH * NTOK * 4];
__device__ uint4 g_khi[BH * NTOK * 4];
__device__ uint4 g_klo[BH * NTOK * 4];
__device__ uint4 g_vhi[BH * NTOK * 4];
__device__ uint4 g_vlo[BH * NTOK * 4];
// attention output bf16 pairs [b][n][128ch] -> 64 uint per row
__device__ unsigned g_ahi[BATCH * NTOK * 64];
__device__ unsigned g_alo[BATCH * NTOK * 64];

// ---------------- helpers ----------------
__device__ __forceinline__ unsigned s2u(const void* p) {
    unsigned r;
    asm("{.reg .u64 t; cvta.to.shared.u64 t,%1; cvt.u32.u64 %0,t;}" : "=r"(r) : "l"(p));
    return r;
}
__device__ __forceinline__ float ex2f(float x) {
    float y; asm("ex2.approx.f32 %0,%1;" : "=f"(y) : "f"(x)); return y;
}
__device__ __forceinline__ void split2(float a, float b, unsigned& h, unsigned& l) {
    unsigned hh; asm("cvt.rn.bf16x2.f32 %0,%1,%2;" : "=r"(hh) : "f"(b), "f"(a));
    float ha = __uint_as_float(hh << 16);
    float hb = __uint_as_float(hh & 0xffff0000u);
    float ra = a - ha, rb = b - hb;
    unsigned ll; asm("cvt.rn.bf16x2.f32 %0,%1,%2;" : "=r"(ll) : "f"(rb), "f"(ra));
    h = hh; l = ll;
}

#define MMA_BF16(d, a0, a1, a2, a3, b0, b1) \
    asm volatile("mma.sync.aligned.m16n8k16.row.col.f32.bf16.bf16.f32 " \
        "{%0,%1,%2,%3},{%4,%5,%6,%7},{%8,%9},{%0,%1,%2,%3};" \
        : "+f"((d)[0]), "+f"((d)[1]), "+f"((d)[2]), "+f"((d)[3]) \
        : "r"(a0), "r"(a1), "r"(a2), "r"(a3), "r"(b0), "r"(b1))

#define LDSM_X4(r0, r1, r2, r3, a) \
    asm volatile("ldmatrix.sync.aligned.m8n8.x4.shared.b16 {%0,%1,%2,%3},[%4];" \
        : "=r"(r0), "=r"(r1), "=r"(r2), "=r"(r3) : "r"(a))
#define LDSM_X4_T(r0, r1, r2, r3, a) \
    asm volatile("ldmatrix.sync.aligned.m8n8.x4.trans.shared.b16 {%0,%1,%2,%3},[%4];" \
        : "=r"(r0), "=r"(r1), "=r"(r2), "=r"(r3) : "r"(a))

#define CP_ASYNC(dst, src) \
    asm volatile("cp.async.cg.shared.global [%0],[%1],16;" :: "r"(dst), "l"(src))
#define CP_COMMIT() asm volatile("cp.async.commit_group;")
#define CP_WAIT(n)  asm volatile("cp.async.wait_group %0;" :: "n"(n) : "memory")

// ============================================================================
// Kernel 0: split x / w_qkv / w_out into bf16 hi/lo pairs
// ============================================================================
#define NX2  (BATCH * CIN * NTOK / 2)
#define NWQ2 (384 * 256 / 2)
#define NWO2 (256 * 128 / 2)

__global__ __launch_bounds__(256) void split_kernel(const float* __restrict__ x,
                                                    const float* __restrict__ wq,
                                                    const float* __restrict__ wo)
{
    int i = blockIdx.x * 256 + threadIdx.x;
    if (i >= NX2 + NWQ2 + NWO2) return;
    const float2* src; unsigned *dh, *dl; int j;
    if (i < NX2)              { j = i;               src = (const float2*)x;  dh = g_xhi;  dl = g_xlo; }
    else if (i < NX2 + NWQ2)  { j = i - NX2;         src = (const float2*)wq; dh = g_wqhi; dl = g_wqlo; }
    else                      { j = i - NX2 - NWQ2;  src = (const float2*)wo; dh = g_wohi; dl = g_wolo; }
    float2 v = src[j];
    unsigned h, l; split2(v.x, v.y, h, l);
    dh[j] = h; dl[j] = l;
}

// ============================================================================
// Kernel 1: QKV projection, HMMA bf16x3. Computes OUT^T: A = x^T, B = w.
// CTA: 256 thr / 8 warps, tile n=128 x o=64, k-slices of 32 double-buffered.
// ============================================================================
#define QX_ROW 272
#define QXL    8704
#define QWH    17408
#define QW_ROW 80
#define QBUF   27648

__global__ __launch_bounds__(256) void qkv_mma()
{
    extern __shared__ unsigned char qs[];
    unsigned sb = s2u(qs);
    int tid = threadIdx.x, lane = tid & 31, wid = tid >> 5;
    int lrow = lane & 7, lmi = lane >> 3;
    int g = lane >> 2, tq = lane & 3;
    int n0 = blockIdx.x * 128, o0 = blockIdx.y * 64, b = blockIdx.z;

    float s[8][4];
    #pragma unroll
    for (int i = 0; i < 8; i++)
        #pragma unroll
        for (int j = 0; j < 4; j++) s[i][j] = 0.f;

    auto load_slice = [&](int ks, int buf) {
        unsigned bb = sb + buf * QBUF;
        #pragma unroll
        for (int i = tid; i < 1024; i += 256) {     // x slice [32c][128n] hi/lo
            int arr = i >> 9, ch = i & 511, c = ch >> 4, c16 = ch & 15;
            unsigned dst = bb + arr * QXL + c * QX_ROW + c16 * 16;
            const char* src = (const char*)(arr ? g_xlo : g_xhi)
                + (((size_t)(b * CIN + ks * 32 + c)) * 2048 + (n0 >> 1) + c16 * 4) * 4;
            CP_ASYNC(dst, src);
        }
        #pragma unroll
        for (int i = tid; i < 512; i += 256) {      // w slice [64o][32c] hi/lo
            int arr = i >> 8, ch = i & 255, o = ch >> 2, c16 = ch & 3;
            unsigned dst = bb + QWH + arr * 5120 + o * QW_ROW + c16 * 16;
            const char* src = (const char*)(arr ? g_wqlo : g_wqhi)
                + (((size_t)(o0 + o)) * 128 + ks * 16 + c16 * 4) * 4;
            CP_ASYNC(dst, src);
        }
        CP_COMMIT();
    };

    load_slice(0, 0);
    for (int ks = 0; ks < 8; ks++) {
        if (ks < 7) { load_slice(ks + 1, (ks + 1) & 1); CP_WAIT(1); }
        else        { CP_WAIT(0); }
        __syncthreads();

        unsigned xb = sb + (ks & 1) * QBUF;
        unsigned wb = xb + QWH;

        // A fragments (x^T via trans ldmatrix), hi/lo, two k16 halves
        unsigned abase = xb + ((unsigned)((lane >> 4) * 8 + lrow)) * QX_ROW
                       + (wid * 16 + ((lane >> 3) & 1) * 8) * 2;
        unsigned axh0[4], axh1[4], axl0[4], axl1[4];
        LDSM_X4_T(axh0[0], axh0[1], axh0[2], axh0[3], abase);
        LDSM_X4_T(axh1[0], axh1[1], axh1[2], axh1[3], abase + 16 * QX_ROW);
        LDSM_X4_T(axl0[0], axl0[1], axl0[2], axl0[3], abase + QXL);
        LDSM_X4_T(axl1[0], axl1[1], axl1[2], axl1[3], abase + QXL + 16 * QX_ROW);

        unsigned bbase = wb + lrow * QW_ROW + lmi * 16;
        #pragma unroll
        for (int ot = 0; ot < 8; ot++) {
            unsigned bh0, bh1, bh2, bh3, bl0, bl1, bl2, bl3;
            unsigned ba = bbase + ot * (8 * QW_ROW);
            LDSM_X4(bh0, bh1, bh2, bh3, ba);
            LDSM_X4(bl0, bl1, bl2, bl3, ba + 5120);
            MMA_BF16(s[ot], axh0[0], axh0[1], axh0[2], axh0[3], bh0, bh1);
            MMA_BF16(s[ot], axl0[0], axl0[1], axl0[2], axl0[3], bh0, bh1);
            MMA_BF16(s[ot], axh0[0], axh0[1], axh0[2], axh0[3], bl0, bl1);
            MMA_BF16(s[ot], axh1[0], axh1[1], axh1[2], axh1[3], bh2, bh3);
            MMA_BF16(s[ot], axl1[0], axl1[1], axl1[2], axl1[3], bh2, bh3);
            MMA_BF16(s[ot], axh1[0], axh1[1], axh1[2], axh1[3], bl2, bl3);
        }
        __syncthreads();
    }

    // Epilogue: D^T rows = n, cols = o. split2 pairs land on channel pairs.
    int nr = n0 + wid * 16 + g;
    #pragma unroll
    for (int ot = 0; ot < 8; ot++) {
        int o = o0 + ot * 8 + 2 * tq;
        int kind = o >> 7, hh = (o >> 5) & 3, c = o & 31;
        unsigned* dh = (unsigned*)(kind == 0 ? g_qhi : (kind == 1 ? g_khi : g_vhi));
        unsigned* dl = (unsigned*)(kind == 0 ? g_qlo : (kind == 1 ? g_klo : g_vlo));
        float sc = (kind == 0) ? QSCALE : 1.f;
        size_t i0 = ((size_t)(b * HEADS + hh) * NTOK + nr) * 16 + (c >> 1);
        unsigned h0, l0;
        split2(s[ot][0] * sc, s[ot][1] * sc, h0, l0);
        dh[i0] = h0; dl[i0] = l0;
        split2(s[ot][2] * sc, s[ot][3] * sc, h0, l0);
        dh[i0 + 128] = h0; dl[i0 + 128] = l0;     // row nr+8
    }
}

// ============================================================================
// Kernel 2: FlashAttention-2 mma.sync bf16x3 (body unchanged; new epilogue)
// ============================================================================
#define ROWB 80
#define ARRB (64 * ROWB)
#define BUFB (4 * ARRB)

struct __align__(16) FSmem { unsigned char kv[2][4][ARRB]; };

__global__ __launch_bounds__(128) void fattn_kernel()
{
    __shared__ FSmem fs;
    unsigned sb = s2u(&fs);
    int tid = threadIdx.x;
    int lane = tid & 31, wid = tid >> 5;
    int qt = blockIdx.x, bh = blockIdx.y;
    int g = lane >> 2, tq = lane & 3;
    int lrow = lane & 7, lmi = lane >> 3;

    const uint4* srcs[4] = {
        g_khi + (size_t)bh * NTOK * 4, g_klo + (size_t)bh * NTOK * 4,
        g_vhi + (size_t)bh * NTOK * 4, g_vlo + (size_t)bh * NTOK * 4 };

    {
        int c16 = tid & 3, r0 = tid >> 2;
        #pragma unroll
        for (int i = 0; i < 8; i++) {
            int arr = i >> 1, row = (r0 + i * 32) & 63;
            unsigned dst = sb + arr * ARRB + row * ROWB + c16 * 16;
            CP_ASYNC(dst, srcs[arr] + (size_t)row * 4 + c16);
        }
        CP_COMMIT();
    }

    unsigned qh[2][4], ql[2][4];
    {
        int qa = qt * 64 + wid * 16 + g;
        const unsigned* ph = (const unsigned*)(g_qhi + ((size_t)bh * NTOK + qa) * 4);
        const unsigned* pl = (const unsigned*)(g_qlo + ((size_t)bh * NTOK + qa) * 4);
        #pragma unroll
        for (int kb = 0; kb < 2; kb++) {
            qh[kb][0] = ph[8 * kb + tq];       qh[kb][2] = ph[8 * kb + 4 + tq];
            qh[kb][1] = ph[128 + 8 * kb + tq]; qh[kb][3] = ph[128 + 8 * kb + 4 + tq];
            ql[kb][0] = pl[8 * kb + tq];       ql[kb][2] = pl[8 * kb + 4 + tq];
            ql[kb][1] = pl[128 + 8 * kb + tq]; ql[kb][3] = pl[128 + 8 * kb + 4 + tq];
        }
    }

    float o[4][4];
    #pragma unroll
    for (int i = 0; i < 4; i++)
        #pragma unroll
        for (int j = 0; j < 4; j++) o[i][j] = 0.f;
    float m_a = -1e30f, m_b = -1e30f, l_a = 0.f, l_b = 0.f;

    int buf = 0;
    for (int kt = 0; kt < NTOK / 64; kt++) {
        if (kt < NTOK / 64 - 1) {
            int c16 = tid & 3, r0 = tid >> 2;
            unsigned bb = sb + (buf ^ 1) * BUFB;
            size_t goff = (size_t)(kt + 1) * 64 * 4;
            #pragma unroll
            for (int i = 0; i < 8; i++) {
                int arr = i >> 1, row = (r0 + i * 32) & 63;
                CP_ASYNC(bb + arr * ARRB + row * ROWB + c16 * 16,
                         srcs[arr] + goff + (size_t)row * 4 + c16);
            }
            CP_COMMIT();
            CP_WAIT(1);
        } else {
            CP_WAIT(0);
        }
        __syncthreads();

        unsigned kb_base = sb + buf * BUFB;

        float s[8][4];
        #pragma unroll
        for (int nb = 0; nb < 8; nb++)
            #pragma unroll
            for (int i = 0; i < 4; i++) s[nb][i] = 0.f;

        #pragma unroll
        for (int nb = 0; nb < 8; nb++) {
            unsigned kh0, kh1, kh2, kh3, kl0, kl1, kl2, kl3;
            unsigned ka = kb_base + (8 * nb + lrow) * ROWB + lmi * 16;
            LDSM_X4(kh0, kh1, kh2, kh3, ka);
            LDSM_X4(kl0, kl1, kl2, kl3, ka + ARRB);
            MMA_BF16(s[nb], qh[0][0], qh[0][1], qh[0][2], qh[0][3], kh0, kh1);
            MMA_BF16(s[nb], qh[1][0], qh[1][1], qh[1][2], qh[1][3], kh2, kh3);
            MMA_BF16(s[nb], ql[0][0], ql[0][1], ql[0][2], ql[0][3], kh0, kh1);
            MMA_BF16(s[nb], ql[1][0], ql[1][1], ql[1][2], ql[1][3], kh2, kh3);
            MMA_BF16(s[nb], qh[0][0], qh[0][1], qh[0][2], qh[0][3], kl0, kl1);
            MMA_BF16(s[nb], qh[1][0], qh[1][1], qh[1][2], qh[1][3], kl2, kl3);
        }

        float mx_a = -1e30f, mx_b = -1e30f;
        #pragma unroll
        for (int nb = 0; nb < 8; nb++) {
            mx_a = fmaxf(mx_a, fmaxf(s[nb][0], s[nb][1]));
            mx_b = fmaxf(mx_b, fmaxf(s[nb][2], s[nb][3]));
        }
        mx_a = fmaxf(mx_a, __shfl_xor_sync(0xffffffffu, mx_a, 1));
        mx_a = fmaxf(mx_a, __shfl_xor_sync(0xffffffffu, mx_a, 2));
        mx_b = fmaxf(mx_b, __shfl_xor_sync(0xffffffffu, mx_b, 1));
        mx_b = fmaxf(mx_b, __shfl_xor_sync(0xffffffffu, mx_b, 2));

        float mna = fmaxf(m_a, mx_a), mnb = fmaxf(m_b, mx_b);
        float ca = ex2f(m_a - mna), cb = ex2f(m_b - mnb);
        m_a = mna; m_b = mnb;
        #pragma unroll
        for (int nb = 0; nb < 4; nb++) {
            o[nb][0] *= ca; o[nb][1] *= ca;
            o[nb][2] *= cb; o[nb][3] *= cb;
        }

        float sa = 0.f, sbm = 0.f;
        #pragma unroll
        for (int nb = 0; nb < 8; nb++) {
            s[nb][0] = ex2f(s[nb][0] - m_a);
            s[nb][1] = ex2f(s[nb][1] - m_a);
            s[nb][2] = ex2f(s[nb][2] - m_b);
            s[nb][3] = ex2f(s[nb][3] - m_b);
            sa += s[nb][0] + s[nb][1];
            sbm += s[nb][2] + s[nb][3];
        }
        sa += __shfl_xor_sync(0xffffffffu, sa, 1);
        sa += __shfl_xor_sync(0xffffffffu, sa, 2);
        sbm += __shfl_xor_sync(0xffffffffu, sbm, 1);
        sbm += __shfl_xor_sync(0xffffffffu, sbm, 2);
        l_a = l_a * ca + sa;
        l_b = l_b * cb + sbm;

        unsigned vbase = kb_base + 2 * ARRB;
        #pragma unroll
        for (int kb = 0; kb < 4; kb++) {
            unsigned ph[4], pl[4];
            split2(s[2 * kb][0],     s[2 * kb][1],     ph[0], pl[0]);
            split2(s[2 * kb][2],     s[2 * kb][3],     ph[1], pl[1]);
            split2(s[2 * kb + 1][0], s[2 * kb + 1][1], ph[2], pl[2]);
            split2(s[2 * kb + 1][2], s[2 * kb + 1][3], ph[3], pl[3]);
            #pragma unroll
            for (int cp = 0; cp < 2; cp++) {
                int oct = 2 * kb + (lmi & 1), chunk = 2 * cp + (lmi >> 1);
                unsigned va = vbase + (oct * 8 + lrow) * ROWB + chunk * 16;
                unsigned vh0, vh1, vh2, vh3, vl0, vl1, vl2, vl3;
                LDSM_X4_T(vh0, vh1, vh2, vh3, va);
                LDSM_X4_T(vl0, vl1, vl2, vl3, va + ARRB);
                MMA_BF16(o[2 * cp],     ph[0], ph[1], ph[2], ph[3], vh0, vh1);
                MMA_BF16(o[2 * cp + 1], ph[0], ph[1], ph[2], ph[3], vh2, vh3);
                MMA_BF16(o[2 * cp],     pl[0], pl[1], pl[2], pl[3], vh0, vh1);
                MMA_BF16(o[2 * cp + 1], pl[0], pl[1], pl[2], pl[3], vh2, vh3);
                MMA_BF16(o[2 * cp],     ph[0], ph[1], ph[2], ph[3], vl0, vl1);
                MMA_BF16(o[2 * cp + 1], ph[0], ph[1], ph[2], ph[3], vl2, vl3);
            }
        }

        __syncthreads();
        buf ^= 1;
    }

    // ---- epilogue: normalize + split to bf16 hi/lo, direct [b][n][128] ----
    float inv_a = 1.f / l_a, inv_b = 1.f / l_b;
    int b = bh >> 2, h = bh & 3;
    int qa = qt * 64 + wid * 16 + g;
    #pragma unroll
    for (int nb = 0; nb < 4; nb++) {
        int c = h * 32 + nb * 8 + 2 * tq;
        size_t i0 = ((size_t)b * NTOK + qa) * 64 + (c >> 1);
        unsigned hA, lA;
        split2(o[nb][0] * inv_a, o[nb][1] * inv_a, hA, lA);
        g_ahi[i0] = hA; g_alo[i0] = lA;
        split2(o[nb][2] * inv_b, o[nb][3] * inv_b, hA, lA);
        g_ahi[i0 + 8 * 64] = hA; g_alo[i0 + 8 * 64] = lA;
    }
}

// ============================================================================
// Kernel 3: output projection, HMMA bf16x3. A = w_out rows, B = attn rows.
// CTA: 256 thr / 8 warps, tile o=64 x n=64, k=128 resident in smem.
// ============================================================================
#define OROW 272
#define OARR 17408

__global__ __launch_bounds__(256) void out_mma(const float* __restrict__ bias,
                                               float* __restrict__ out)
{
    extern __shared__ unsigned char osm[];
    unsigned sb = s2u(osm);
    int tid = threadIdx.x, lane = tid & 31, wid = tid >> 5;
    int lrow = lane & 7, lmi = lane >> 3;
    int g = lane >> 2, tq = lane & 3;
    int n0 = blockIdx.x * 64, o0 = blockIdx.y * 64, b = blockIdx.z;

    #pragma unroll
    for (int i = tid; i < 4096; i += 256) {
        int arr = i >> 10, ch = i & 1023, r = ch >> 4, c16 = ch & 15;
        unsigned dst = sb + arr * OARR + r * OROW + c16 * 16;
        const char* src;
        if (arr < 2)
            src = (const char*)(arr ? g_wolo : g_wohi)
                + (((size_t)(o0 + r)) * 64 + c16 * 4) * 4;
        else
            src = (const char*)(arr == 2 ? g_ahi : g_alo)
                + (((size_t)(b * NTOK + n0 + r)) * 64 + c16 * 4) * 4;
        CP_ASYNC(dst, src);
    }
    CP_COMMIT(); CP_WAIT(0);
    __syncthreads();

    int ow = wid >> 1, nh = wid & 1;
    float s[4][4];
    #pragma unroll
    for (int i = 0; i < 4; i++)
        #pragma unroll
        for (int j = 0; j < 4; j++) s[i][j] = 0.f;

    unsigned abase = sb + (ow * 16 + (lane & 15)) * OROW + (lane >> 4) * 16;
    unsigned bbase = sb + 2 * OARR + (nh * 32 + lrow) * OROW + lmi * 16;

    #pragma unroll
    for (int ksl = 0; ksl < 4; ksl++) {
        unsigned axh0[4], axh1[4], axl0[4], axl1[4];
        LDSM_X4(axh0[0], axh0[1], axh0[2], axh0[3], abase + ksl * 64);
        LDSM_X4(axh1[0], axh1[1], axh1[2], axh1[3], abase + ksl * 64 + 32);
        LDSM_X4(axl0[0], axl0[1], axl0[2], axl0[3], abase + OARR + ksl * 64);
        LDSM_X4(axl1[0], axl1[1], axl1[2], axl1[3], abase + OARR + ksl * 64 + 32);
        #pragma unroll
        for (int nt = 0; nt < 4; nt++) {
            unsigned bh0, bh1, bh2, bh3, bl0, bl1, bl2, bl3;
            unsigned ba = bbase + nt * (8 * OROW) + ksl * 64;
            LDSM_X4(bh0, bh1, bh2, bh3, ba);
            LDSM_X4(bl0, bl1, bl2, bl3, ba + OARR);
            MMA_BF16(s[nt], axh0[0], axh0[1], axh0[2], axh0[3], bh0, bh1);
            MMA_BF16(s[nt], axl0[0], axl0[1], axl0[2], axl0[3], bh0, bh1);
            MMA_BF16(s[nt], axh0[0], axh0[1], axh0[2], axh0[3], bl0, bl1);
            MMA_BF16(s[nt], axh1[0], axh1[1], axh1[2], axh1[3], bh2, bh3);
            MMA_BF16(s[nt], axl1[0], axl1[1], axl1[2], axl1[3], bh2, bh3);
            MMA_BF16(s[nt], axh1[0], axh1[1], axh1[2], axh1[3], bl2, bl3);
        }
    }

    int o = o0 + ow * 16 + g;
    float b0 = bias[o], b1 = bias[o + 8];
    #pragma unroll
    for (int nt = 0; nt < 4; nt++) {
        int n = n0 + nh * 32 + nt * 8 + 2 * tq;
        *(float2*)&out[((size_t)(b * CIN + o)) * NTOK + n] =
            make_float2(s[nt][0] + b0, s[nt][1] + b0);
        *(float2*)&out[((size_t)(b * CIN + o + 8)) * NTOK + n] =
            make_float2(s[nt][2] + b1, s[nt][3] + b1);
    }
}

// ============================================================================
extern "C" void kernel_launch(void* const* d_in, const int* in_sizes, int n_in,
                              void* d_out, int out_size)
{
    (void)in_sizes; (void)n_in; (void)out_size;
    const float* x     = (const float*)d_in[0];
    const float* w_qkv = (const float*)d_in[1];
    const float* w_out = (const float*)d_in[2];
    const float* b_out = (const float*)d_in[3];
    float* out = (float*)d_out;

    cudaFuncSetAttribute(qkv_mma, cudaFuncAttributeMaxDynamicSharedMemorySize, 2 * QBUF);
    cudaFuncSetAttribute(out_mma, cudaFuncAttributeMaxDynamicSharedMemorySize, 4 * OARR);

    int total = NX2 + NWQ2 + NWO2;
    split_kernel<<<(total + 255) / 256, 256>>>(x, w_qkv, w_out);
    qkv_mma<<<dim3(32, 6, 4), 256, 2 * QBUF>>>();
    fattn_kernel<<<dim3(NTOK / 64, BH), 128>>>();
    out_mma<<<dim3(64, 4, 4), 256, 4 * OARR>>>(b_out, out);
}